// round 1
// baseline (speedup 1.0000x reference)
#include <cuda_runtime.h>
#include <math.h>

#define TOKS 512
#define HDIM 1024
#define FDIM 4096
#define NEXP 8
#define SLOT 512

// ---------------- scratch (static device globals; no runtime allocation) ----
__device__ float d_h[NEXP * SLOT * FDIM];    // 64 MB padded intermediate h
__device__ float d_po[NEXP * SLOT * HDIM];   // 16 MB pair outputs (scaled)
__device__ int   d_count[NEXP];
__device__ int   d_tok[NEXP * SLOT];
__device__ float d_mult[NEXP * SLOT];
__device__ int   d_pidx[TOKS * 2];

// ---------------- init ------------------------------------------------------
__global__ void init_kernel() {
    if (threadIdx.x < NEXP) d_count[threadIdx.x] = 0;
}

// ---------------- routing ---------------------------------------------------
__global__ void routing_kernel(const float* __restrict__ x,
                               const float* __restrict__ gw) {
    int t = blockIdx.x;
    int tid = threadIdx.x;
    int w = tid >> 5, lane = tid & 31;
    __shared__ float lg[NEXP];

    // 8 warps -> 8 experts; dot(x[t], gate_w[e]) over 1024
    const float* xr = x + (size_t)t * HDIM;
    const float* gr = gw + (size_t)w * HDIM;
    float s = 0.f;
    for (int i = lane * 4; i < HDIM; i += 128) {
        float4 a = *(const float4*)(xr + i);
        float4 b = *(const float4*)(gr + i);
        s += a.x * b.x + a.y * b.y + a.z * b.z + a.w * b.w;
    }
    #pragma unroll
    for (int o = 16; o; o >>= 1) s += __shfl_xor_sync(0xFFFFFFFFu, s, o);
    if (lane == 0) lg[w] = s;
    __syncthreads();

    if (tid == 0) {
        float l[NEXP];
        #pragma unroll
        for (int e = 0; e < NEXP; e++) l[e] = lg[e];

        // top-1 / top-2 with first-index tie-break (matches lax.top_k)
        int s1 = 0;
        for (int e = 1; e < NEXP; e++) if (l[e] > l[s1]) s1 = e;
        float m1 = l[s1];
        int s2 = (s1 == 0) ? 1 : 0;
        for (int e = 0; e < NEXP; e++) { if (e == s1) continue; if (l[e] > l[s2]) s2 = e; }
        float m2 = l[s2];

        float mult1, mult2;
        {   // softmax with jitter mask vs m1
            float keep[NEXP]; float mx = -1e30f;
            for (int e = 0; e < NEXP; e++) {
                float f = fmaxf(fabsf(l[e]), m1);
                keep[e] = ((m1 - l[e]) / f > 0.02f) ? -1e30f : l[e];
                mx = fmaxf(mx, keep[e]);
            }
            float sum = 0.f, num = 0.f;
            for (int e = 0; e < NEXP; e++) {
                float p = (keep[e] <= -1e30f) ? 0.f : expf(keep[e] - mx);
                sum += p; if (e == s1) num = p;
            }
            mult1 = num / sum;
        }
        {   // softmax with jitter mask vs m2, dropping top-1
            float keep[NEXP]; float mx = -1e30f;
            for (int e = 0; e < NEXP; e++) {
                float f = fmaxf(fabsf(l[e]), m2);
                bool msk = ((m2 - l[e]) / f > 0.02f) || (e == s1);
                keep[e] = msk ? -1e30f : l[e];
                mx = fmaxf(mx, keep[e]);
            }
            float sum = 0.f, num = 0.f;
            for (int e = 0; e < NEXP; e++) {
                float p = (keep[e] <= -1e30f) ? 0.f : expf(keep[e] - mx);
                sum += p; if (e == s2) num = p;
            }
            mult2 = num / sum;
        }

        int p = atomicAdd(&d_count[s1], 1);
        d_tok[s1 * SLOT + p] = t; d_mult[s1 * SLOT + p] = mult1;
        d_pidx[t * 2 + 0] = s1 * SLOT + p;
        p = atomicAdd(&d_count[s2], 1);
        d_tok[s2 * SLOT + p] = t; d_mult[s2 * SLOT + p] = mult2;
        d_pidx[t * 2 + 1] = s2 * SLOT + p;
    }
}

// ---------------- tf32 mma helpers -----------------------------------------
__device__ __forceinline__ unsigned f2tf(float f) {
    unsigned u; asm("cvt.rna.tf32.f32 %0, %1;" : "=r"(u) : "f"(f)); return u;
}
__device__ __forceinline__ void mma8(float* c, const unsigned* a, const unsigned* b) {
    asm volatile(
        "mma.sync.aligned.m16n8k8.row.col.f32.tf32.tf32.f32 "
        "{%0,%1,%2,%3}, {%4,%5,%6,%7}, {%8,%9}, {%0,%1,%2,%3};"
        : "+f"(c[0]), "+f"(c[1]), "+f"(c[2]), "+f"(c[3])
        : "r"(a[0]), "r"(a[1]), "r"(a[2]), "r"(a[3]), "r"(b[0]), "r"(b[1]));
}

#define BM 64
#define BN 64
#define BK 16
#define SST 20   // BK + 4 pad (floats) -> conflict-free fragment reads

// ---------------- GEMM1: h = silu(x@w1^T) * (x@w3^T), grouped per expert ----
__global__ __launch_bounds__(256) void gemm1_kernel(const float* __restrict__ x,
                                                    const float* __restrict__ w1,
                                                    const float* __restrict__ w3) {
    int e = blockIdx.y >> 3, mtile = blockIdx.y & 7;
    int cnt = d_count[e];
    int m0 = mtile * BM;
    if (m0 >= cnt) return;
    int n0 = blockIdx.x * BN;

    __shared__ unsigned As[BM * SST], B1s[BN * SST], B3s[BN * SST];

    int tid = threadIdx.x;
    int row = tid >> 2, c4 = tid & 3;
    int r = m0 + row; if (r >= cnt) r = cnt - 1;           // clamp gather
    int tok = d_tok[e * SLOT + r];
    const float* ap  = x  + (size_t)tok * HDIM + c4 * 4;
    const float* b1p = w1 + ((size_t)e * FDIM + n0 + row) * HDIM + c4 * 4;
    const float* b3p = w3 + ((size_t)e * FDIM + n0 + row) * HDIM + c4 * 4;

    int warp = tid >> 5, lane = tid & 31;
    int wm = warp >> 2, wn = warp & 3;
    int g = lane >> 2, tg = lane & 3;

    float acc1[2][2][4] = {}, acc3[2][2][4] = {};

    float4 ra  = *(const float4*)ap;
    float4 rb1 = *(const float4*)b1p;
    float4 rb3 = *(const float4*)b3p;

    int srow = row * SST + c4 * 4;
    const int NKT = HDIM / BK;
    for (int kt = 0; kt < NKT; kt++) {
        { uint4 u; u.x=f2tf(ra.x);  u.y=f2tf(ra.y);  u.z=f2tf(ra.z);  u.w=f2tf(ra.w);  *(uint4*)&As[srow]  = u; }
        { uint4 u; u.x=f2tf(rb1.x); u.y=f2tf(rb1.y); u.z=f2tf(rb1.z); u.w=f2tf(rb1.w); *(uint4*)&B1s[srow] = u; }
        { uint4 u; u.x=f2tf(rb3.x); u.y=f2tf(rb3.y); u.z=f2tf(rb3.z); u.w=f2tf(rb3.w); *(uint4*)&B3s[srow] = u; }
        __syncthreads();
        if (kt + 1 < NKT) {                       // prefetch next stage
            ra  = *(const float4*)(ap  + (kt + 1) * BK);
            rb1 = *(const float4*)(b1p + (kt + 1) * BK);
            rb3 = *(const float4*)(b3p + (kt + 1) * BK);
        }
        #pragma unroll
        for (int ks = 0; ks < 2; ks++) {
            int k0 = ks * 8;
            unsigned af[2][4];
            #pragma unroll
            for (int mi = 0; mi < 2; mi++) {
                int rb = wm * 32 + mi * 16;
                af[mi][0] = As[(rb + g)     * SST + k0 + tg];
                af[mi][1] = As[(rb + g + 8) * SST + k0 + tg];
                af[mi][2] = As[(rb + g)     * SST + k0 + tg + 4];
                af[mi][3] = As[(rb + g + 8) * SST + k0 + tg + 4];
            }
            #pragma unroll
            for (int ni = 0; ni < 2; ni++) {
                int nb = wn * 16 + ni * 8;
                unsigned bf1[2] = { B1s[(nb + g) * SST + k0 + tg], B1s[(nb + g) * SST + k0 + tg + 4] };
                unsigned bf3[2] = { B3s[(nb + g) * SST + k0 + tg], B3s[(nb + g) * SST + k0 + tg + 4] };
                #pragma unroll
                for (int mi = 0; mi < 2; mi++) {
                    mma8(acc1[mi][ni], af[mi], bf1);
                    mma8(acc3[mi][ni], af[mi], bf3);
                }
            }
        }
        __syncthreads();
    }

    // epilogue: silu(s1) * s3 -> d_h
    #pragma unroll
    for (int mi = 0; mi < 2; mi++)
    #pragma unroll
    for (int ni = 0; ni < 2; ni++)
    #pragma unroll
    for (int h = 0; h < 2; h++) {
        int lr = wm * 32 + mi * 16 + g + h * 8;
        if (m0 + lr < cnt) {
            int col = n0 + wn * 16 + ni * 8 + tg * 2;
            float v1a = acc1[mi][ni][h * 2], v1b = acc1[mi][ni][h * 2 + 1];
            float v3a = acc3[mi][ni][h * 2], v3b = acc3[mi][ni][h * 2 + 1];
            float h0 = v1a * v3a / (1.f + __expf(-v1a));
            float h1 = v1b * v3b / (1.f + __expf(-v1b));
            float2 o; o.x = h0; o.y = h1;
            *(float2*)&d_h[((size_t)(e * SLOT + m0 + lr)) * FDIM + col] = o;
        }
    }
}

// ---------------- GEMM2: po = mult * (h @ w2^T), grouped per expert ---------
__global__ __launch_bounds__(256) void gemm2_kernel(const float* __restrict__ w2) {
    int e = blockIdx.y >> 3, mtile = blockIdx.y & 7;
    int cnt = d_count[e];
    int m0 = mtile * BM;
    if (m0 >= cnt) return;
    int n0 = blockIdx.x * BN;

    __shared__ unsigned As[BM * SST], Bs[BN * SST];

    int tid = threadIdx.x;
    int row = tid >> 2, c4 = tid & 3;
    int r = m0 + row; if (r >= cnt) r = cnt - 1;
    const float* ap = d_h + ((size_t)(e * SLOT) + r) * FDIM + c4 * 4;
    const float* bp = w2 + ((size_t)e * HDIM + n0 + row) * FDIM + c4 * 4;

    int warp = tid >> 5, lane = tid & 31;
    int wm = warp >> 2, wn = warp & 3;
    int g = lane >> 2, tg = lane & 3;

    float acc[2][2][4] = {};

    float4 ra = *(const float4*)ap;
    float4 rb = *(const float4*)bp;

    int srow = row * SST + c4 * 4;
    const int NKT = FDIM / BK;
    for (int kt = 0; kt < NKT; kt++) {
        { uint4 u; u.x=f2tf(ra.x); u.y=f2tf(ra.y); u.z=f2tf(ra.z); u.w=f2tf(ra.w); *(uint4*)&As[srow] = u; }
        { uint4 u; u.x=f2tf(rb.x); u.y=f2tf(rb.y); u.z=f2tf(rb.z); u.w=f2tf(rb.w); *(uint4*)&Bs[srow] = u; }
        __syncthreads();
        if (kt + 1 < NKT) {
            ra = *(const float4*)(ap + (kt + 1) * BK);
            rb = *(const float4*)(bp + (kt + 1) * BK);
        }
        #pragma unroll
        for (int ks = 0; ks < 2; ks++) {
            int k0 = ks * 8;
            unsigned af[2][4];
            #pragma unroll
            for (int mi = 0; mi < 2; mi++) {
                int rbase = wm * 32 + mi * 16;
                af[mi][0] = As[(rbase + g)     * SST + k0 + tg];
                af[mi][1] = As[(rbase + g + 8) * SST + k0 + tg];
                af[mi][2] = As[(rbase + g)     * SST + k0 + tg + 4];
                af[mi][3] = As[(rbase + g + 8) * SST + k0 + tg + 4];
            }
            #pragma unroll
            for (int ni = 0; ni < 2; ni++) {
                int nb = wn * 16 + ni * 8;
                unsigned bf[2] = { Bs[(nb + g) * SST + k0 + tg], Bs[(nb + g) * SST + k0 + tg + 4] };
                #pragma unroll
                for (int mi = 0; mi < 2; mi++) mma8(acc[mi][ni], af[mi], bf);
            }
        }
        __syncthreads();
    }

    #pragma unroll
    for (int mi = 0; mi < 2; mi++)
    #pragma unroll
    for (int ni = 0; ni < 2; ni++)
    #pragma unroll
    for (int h = 0; h < 2; h++) {
        int lr = wm * 32 + mi * 16 + g + h * 8;
        if (m0 + lr < cnt) {
            float mult = d_mult[e * SLOT + m0 + lr];
            int col = n0 + wn * 16 + ni * 8 + tg * 2;
            float2 o;
            o.x = acc[mi][ni][h * 2]     * mult;
            o.y = acc[mi][ni][h * 2 + 1] * mult;
            *(float2*)&d_po[((size_t)(e * SLOT + m0 + lr)) * HDIM + col] = o;
        }
    }
}

// ---------------- finalize: out[t] = po[pair0] + po[pair1] ------------------
__global__ void finalize_kernel(float* __restrict__ out) {
    int t = blockIdx.x;
    int i = threadIdx.x;            // 256 threads x float4 = 1024 floats
    int p0 = d_pidx[t * 2], p1 = d_pidx[t * 2 + 1];
    float4 a = ((const float4*)(d_po + (size_t)p0 * HDIM))[i];
    float4 b = ((const float4*)(d_po + (size_t)p1 * HDIM))[i];
    float4 o; o.x = a.x + b.x; o.y = a.y + b.y; o.z = a.z + b.z; o.w = a.w + b.w;
    ((float4*)(out + (size_t)t * HDIM))[i] = o;
}

// ---------------- launch ----------------------------------------------------
extern "C" void kernel_launch(void* const* d_in, const int* in_sizes, int n_in,
                              void* d_out, int out_size) {
    const float* x  = (const float*)d_in[0];
    const float* gw = (const float*)d_in[1];
    const float* w1 = (const float*)d_in[2];
    const float* w2 = (const float*)d_in[3];
    const float* w3 = (const float*)d_in[4];
    float* out = (float*)d_out;

    init_kernel<<<1, 32>>>();
    routing_kernel<<<TOKS, 256>>>(x, gw);
    gemm1_kernel<<<dim3(FDIM / BN, NEXP * 8), 256>>>(x, w1, w3);
    gemm2_kernel<<<dim3(HDIM / BN, NEXP * 8), 256>>>(w2);
    finalize_kernel<<<TOKS, 256>>>(out);
}

// round 3
// speedup vs baseline: 1.7420x; 1.7420x over previous
#include <cuda_runtime.h>
#include <cstdint>
#include <math.h>

#define TOKS 512
#define HDIM 1024
#define FDIM 4096
#define NEXP 8
#define SLOT 512
#define SST  36              // 32 + 4 pad floats per smem row (conflict-free)
#define STG_F (64 * SST)     // floats per stage per tile (2304)
#define STG_B (STG_F * 4)    // bytes per stage per tile (9216)

// ---------------- scratch (static device globals) ---------------------------
__device__ float d_h[NEXP * SLOT * FDIM];          // 64 MB intermediate h
__device__ float d_po2[2 * NEXP * SLOT * HDIM];    // 32 MB split-K partials
__device__ int   d_count[NEXP];
__device__ int   d_tok[NEXP * SLOT];
__device__ float d_mult[NEXP * SLOT];
__device__ int   d_pidx[TOKS * 2];

// ---------------- init ------------------------------------------------------
__global__ void init_kernel() {
    if (threadIdx.x < NEXP) d_count[threadIdx.x] = 0;
}

// ---------------- routing ---------------------------------------------------
__global__ void routing_kernel(const float* __restrict__ x,
                               const float* __restrict__ gw) {
    int t = blockIdx.x;
    int tid = threadIdx.x;
    int w = tid >> 5, lane = tid & 31;
    __shared__ float lg[NEXP];

    const float* xr = x + (size_t)t * HDIM;
    const float* gr = gw + (size_t)w * HDIM;
    float s = 0.f;
    for (int i = lane * 4; i < HDIM; i += 128) {
        float4 a = *(const float4*)(xr + i);
        float4 b = *(const float4*)(gr + i);
        s += a.x * b.x + a.y * b.y + a.z * b.z + a.w * b.w;
    }
    #pragma unroll
    for (int o = 16; o; o >>= 1) s += __shfl_xor_sync(0xFFFFFFFFu, s, o);
    if (lane == 0) lg[w] = s;
    __syncthreads();

    if (tid == 0) {
        float l[NEXP];
        #pragma unroll
        for (int e = 0; e < NEXP; e++) l[e] = lg[e];

        int s1 = 0;
        for (int e = 1; e < NEXP; e++) if (l[e] > l[s1]) s1 = e;
        float m1 = l[s1];
        int s2 = (s1 == 0) ? 1 : 0;
        for (int e = 0; e < NEXP; e++) { if (e == s1) continue; if (l[e] > l[s2]) s2 = e; }
        float m2 = l[s2];

        float mult1, mult2;
        {
            float keep[NEXP]; float mx = -1e30f;
            for (int e = 0; e < NEXP; e++) {
                float f = fmaxf(fabsf(l[e]), m1);
                keep[e] = ((m1 - l[e]) / f > 0.02f) ? -1e30f : l[e];
                mx = fmaxf(mx, keep[e]);
            }
            float sum = 0.f, num = 0.f;
            for (int e = 0; e < NEXP; e++) {
                float p = (keep[e] <= -1e30f) ? 0.f : expf(keep[e] - mx);
                sum += p; if (e == s1) num = p;
            }
            mult1 = num / sum;
        }
        {
            float keep[NEXP]; float mx = -1e30f;
            for (int e = 0; e < NEXP; e++) {
                float f = fmaxf(fabsf(l[e]), m2);
                bool msk = ((m2 - l[e]) / f > 0.02f) || (e == s1);
                keep[e] = msk ? -1e30f : l[e];
                mx = fmaxf(mx, keep[e]);
            }
            float sum = 0.f, num = 0.f;
            for (int e = 0; e < NEXP; e++) {
                float p = (keep[e] <= -1e30f) ? 0.f : expf(keep[e] - mx);
                sum += p; if (e == s2) num = p;
            }
            mult2 = num / sum;
        }

        int p = atomicAdd(&d_count[s1], 1);
        d_tok[s1 * SLOT + p] = t; d_mult[s1 * SLOT + p] = mult1;
        d_pidx[t * 2 + 0] = s1 * SLOT + p;
        p = atomicAdd(&d_count[s2], 1);
        d_tok[s2 * SLOT + p] = t; d_mult[s2 * SLOT + p] = mult2;
        d_pidx[t * 2 + 1] = s2 * SLOT + p;
    }
}

// ---------------- tf32 mma + cp.async helpers -------------------------------
__device__ __forceinline__ unsigned f2tf(float f) {
    unsigned u; asm("cvt.rna.tf32.f32 %0, %1;" : "=r"(u) : "f"(f)); return u;
}
__device__ __forceinline__ void mma8(float* c, const unsigned* a, const unsigned* b) {
    asm volatile(
        "mma.sync.aligned.m16n8k8.row.col.f32.tf32.tf32.f32 "
        "{%0,%1,%2,%3}, {%4,%5,%6,%7}, {%8,%9}, {%0,%1,%2,%3};"
        : "+f"(c[0]), "+f"(c[1]), "+f"(c[2]), "+f"(c[3])
        : "r"(a[0]), "r"(a[1]), "r"(a[2]), "r"(a[3]), "r"(b[0]), "r"(b[1]));
}
__device__ __forceinline__ void cpa(unsigned dst, const float* src) {
    asm volatile("cp.async.cg.shared.global [%0], [%1], 16;" :: "r"(dst), "l"(src));
}
#define CP_COMMIT asm volatile("cp.async.commit_group;")
#define CP_WAIT1  asm volatile("cp.async.wait_group 1;")

// ---------------- GEMM1: h = silu(x@w1^T) * (x@w3^T), grouped per expert ----
// 64x64 tile (both w1 and w3), BK=32, 3-stage cp.async pipeline.
__global__ __launch_bounds__(256) void gemm1_kernel(const float* __restrict__ x,
                                                    const float* __restrict__ w1,
                                                    const float* __restrict__ w3) {
    extern __shared__ float sm[];
    float* As  = sm;
    float* B1s = sm + 3 * STG_F;
    float* B3s = sm + 6 * STG_F;

    int e = blockIdx.y >> 3, mtile = blockIdx.y & 7;
    int cnt = d_count[e];
    int m0 = mtile * 64;
    if (m0 >= cnt) return;
    int n0 = blockIdx.x * 64;

    int tid = threadIdx.x;
    int rowA0 = tid >> 3, rowA1 = rowA0 + 32, q = tid & 7;
    int r0 = m0 + rowA0; if (r0 >= cnt) r0 = cnt - 1;
    int r1 = m0 + rowA1; if (r1 >= cnt) r1 = cnt - 1;

    const float* a0  = x  + (size_t)d_tok[e * SLOT + r0] * HDIM + q * 4;
    const float* a1  = x  + (size_t)d_tok[e * SLOT + r1] * HDIM + q * 4;
    const float* b10 = w1 + ((size_t)e * FDIM + n0 + rowA0) * HDIM + q * 4;
    const float* b11 = b10 + (size_t)32 * HDIM;
    const float* b30 = w3 + ((size_t)e * FDIM + n0 + rowA0) * HDIM + q * 4;
    const float* b31 = b30 + (size_t)32 * HDIM;

    unsigned sA  = (unsigned)__cvta_generic_to_shared(As);
    unsigned sB1 = (unsigned)__cvta_generic_to_shared(B1s);
    unsigned sB3 = (unsigned)__cvta_generic_to_shared(B3s);
    unsigned off0 = (unsigned)(rowA0 * SST + q * 4) * 4;
    unsigned off1 = (unsigned)(rowA1 * SST + q * 4) * 4;

    const int NKT = HDIM / 32;  // 32

    // prologue: stages 0,1
    #pragma unroll
    for (int s = 0; s < 2; s++) {
        int ko = s * 32;
        unsigned so = (unsigned)s * STG_B;
        cpa(sA  + so + off0, a0  + ko); cpa(sA  + so + off1, a1  + ko);
        cpa(sB1 + so + off0, b10 + ko); cpa(sB1 + so + off1, b11 + ko);
        cpa(sB3 + so + off0, b30 + ko); cpa(sB3 + so + off1, b31 + ko);
        CP_COMMIT;
    }

    int warp = tid >> 5, lane = tid & 31;
    int wm = warp >> 2, wn = warp & 3;
    int g = lane >> 2, tg = lane & 3;

    float acc1[2][2][4] = {}, acc3[2][2][4] = {};

    for (int kt = 0; kt < NKT; kt++) {
        CP_WAIT1;
        __syncthreads();
        int kn = kt + 2;
        if (kn < NKT) {
            int ko = kn * 32;
            unsigned so = (unsigned)(kn % 3) * STG_B;
            cpa(sA  + so + off0, a0  + ko); cpa(sA  + so + off1, a1  + ko);
            cpa(sB1 + so + off0, b10 + ko); cpa(sB1 + so + off1, b11 + ko);
            cpa(sB3 + so + off0, b30 + ko); cpa(sB3 + so + off1, b31 + ko);
        }
        CP_COMMIT;

        const float* cA  = As  + (kt % 3) * STG_F;
        const float* cB1 = B1s + (kt % 3) * STG_F;
        const float* cB3 = B3s + (kt % 3) * STG_F;

        #pragma unroll
        for (int ks = 0; ks < 4; ks++) {
            int k0 = ks * 8;
            unsigned af[2][4];
            #pragma unroll
            for (int mi = 0; mi < 2; mi++) {
                int rb = wm * 32 + mi * 16;
                af[mi][0] = f2tf(cA[(rb + g)     * SST + k0 + tg]);
                af[mi][1] = f2tf(cA[(rb + g + 8) * SST + k0 + tg]);
                af[mi][2] = f2tf(cA[(rb + g)     * SST + k0 + tg + 4]);
                af[mi][3] = f2tf(cA[(rb + g + 8) * SST + k0 + tg + 4]);
            }
            #pragma unroll
            for (int ni = 0; ni < 2; ni++) {
                int nb = wn * 16 + ni * 8;
                unsigned bf1[2] = { f2tf(cB1[(nb + g) * SST + k0 + tg]),
                                    f2tf(cB1[(nb + g) * SST + k0 + tg + 4]) };
                unsigned bf3[2] = { f2tf(cB3[(nb + g) * SST + k0 + tg]),
                                    f2tf(cB3[(nb + g) * SST + k0 + tg + 4]) };
                #pragma unroll
                for (int mi = 0; mi < 2; mi++) {
                    mma8(acc1[mi][ni], af[mi], bf1);
                    mma8(acc3[mi][ni], af[mi], bf3);
                }
            }
        }
    }

    // epilogue: silu(s1) * s3 -> d_h
    #pragma unroll
    for (int mi = 0; mi < 2; mi++)
    #pragma unroll
    for (int ni = 0; ni < 2; ni++)
    #pragma unroll
    for (int h = 0; h < 2; h++) {
        int lr = wm * 32 + mi * 16 + g + h * 8;
        if (m0 + lr < cnt) {
            int col = n0 + wn * 16 + ni * 8 + tg * 2;
            float v1a = acc1[mi][ni][h * 2], v1b = acc1[mi][ni][h * 2 + 1];
            float v3a = acc3[mi][ni][h * 2], v3b = acc3[mi][ni][h * 2 + 1];
            float h0 = v1a * v3a / (1.f + __expf(-v1a));
            float h1 = v1b * v3b / (1.f + __expf(-v1b));
            float2 o; o.x = h0; o.y = h1;
            *(float2*)&d_h[((size_t)(e * SLOT + m0 + lr)) * FDIM + col] = o;
        }
    }
}

// ---------------- GEMM2: po = mult * (h @ w2^T), split-K x2 -----------------
__global__ __launch_bounds__(256) void gemm2_kernel(const float* __restrict__ w2) {
    extern __shared__ float sm[];
    float* As = sm;
    float* Bs = sm + 3 * STG_F;

    int e = blockIdx.y >> 3, mtile = blockIdx.y & 7;
    int cnt = d_count[e];
    int m0 = mtile * 64;
    if (m0 >= cnt) return;
    int n0 = blockIdx.x * 64;
    int kz = blockIdx.z;                  // 0 or 1
    int kbase = kz * (FDIM / 2);

    int tid = threadIdx.x;
    int rowA0 = tid >> 3, rowA1 = rowA0 + 32, q = tid & 7;
    int r0 = m0 + rowA0; if (r0 >= cnt) r0 = cnt - 1;
    int r1 = m0 + rowA1; if (r1 >= cnt) r1 = cnt - 1;

    const float* a0 = d_h + ((size_t)(e * SLOT) + r0) * FDIM + kbase + q * 4;
    const float* a1 = d_h + ((size_t)(e * SLOT) + r1) * FDIM + kbase + q * 4;
    const float* b0 = w2 + ((size_t)e * HDIM + n0 + rowA0) * FDIM + kbase + q * 4;
    const float* b1 = b0 + (size_t)32 * FDIM;

    unsigned sA = (unsigned)__cvta_generic_to_shared(As);
    unsigned sB = (unsigned)__cvta_generic_to_shared(Bs);
    unsigned off0 = (unsigned)(rowA0 * SST + q * 4) * 4;
    unsigned off1 = (unsigned)(rowA1 * SST + q * 4) * 4;

    const int NKT = (FDIM / 2) / 32;  // 64

    #pragma unroll
    for (int s = 0; s < 2; s++) {
        int ko = s * 32;
        unsigned so = (unsigned)s * STG_B;
        cpa(sA + so + off0, a0 + ko); cpa(sA + so + off1, a1 + ko);
        cpa(sB + so + off0, b0 + ko); cpa(sB + so + off1, b1 + ko);
        CP_COMMIT;
    }

    int warp = tid >> 5, lane = tid & 31;
    int wm = warp >> 2, wn = warp & 3;
    int g = lane >> 2, tg = lane & 3;

    float acc[2][2][4] = {};

    for (int kt = 0; kt < NKT; kt++) {
        CP_WAIT1;
        __syncthreads();
        int kn = kt + 2;
        if (kn < NKT) {
            int ko = kn * 32;
            unsigned so = (unsigned)(kn % 3) * STG_B;
            cpa(sA + so + off0, a0 + ko); cpa(sA + so + off1, a1 + ko);
            cpa(sB + so + off0, b0 + ko); cpa(sB + so + off1, b1 + ko);
        }
        CP_COMMIT;

        const float* cA = As + (kt % 3) * STG_F;
        const float* cB = Bs + (kt % 3) * STG_F;

        #pragma unroll
        for (int ks = 0; ks < 4; ks++) {
            int k0 = ks * 8;
            unsigned af[2][4];
            #pragma unroll
            for (int mi = 0; mi < 2; mi++) {
                int rb = wm * 32 + mi * 16;
                af[mi][0] = f2tf(cA[(rb + g)     * SST + k0 + tg]);
                af[mi][1] = f2tf(cA[(rb + g + 8) * SST + k0 + tg]);
                af[mi][2] = f2tf(cA[(rb + g)     * SST + k0 + tg + 4]);
                af[mi][3] = f2tf(cA[(rb + g + 8) * SST + k0 + tg + 4]);
            }
            #pragma unroll
            for (int ni = 0; ni < 2; ni++) {
                int nb = wn * 16 + ni * 8;
                unsigned bf[2] = { f2tf(cB[(nb + g) * SST + k0 + tg]),
                                   f2tf(cB[(nb + g) * SST + k0 + tg + 4]) };
                #pragma unroll
                for (int mi = 0; mi < 2; mi++) mma8(acc[mi][ni], af[mi], bf);
            }
        }
    }

    float* po = d_po2 + (size_t)kz * (NEXP * SLOT * HDIM);
    #pragma unroll
    for (int mi = 0; mi < 2; mi++)
    #pragma unroll
    for (int ni = 0; ni < 2; ni++)
    #pragma unroll
    for (int h = 0; h < 2; h++) {
        int lr = wm * 32 + mi * 16 + g + h * 8;
        if (m0 + lr < cnt) {
            float mult = d_mult[e * SLOT + m0 + lr];
            int col = n0 + wn * 16 + ni * 8 + tg * 2;
            float2 o;
            o.x = acc[mi][ni][h * 2]     * mult;
            o.y = acc[mi][ni][h * 2 + 1] * mult;
            *(float2*)&po[((size_t)(e * SLOT + m0 + lr)) * HDIM + col] = o;
        }
    }
}

// ---------------- finalize: out[t] = sum of split-K partials over both experts
__global__ void finalize_kernel(float* __restrict__ out) {
    int t = blockIdx.x;
    int i = threadIdx.x;  // 256 threads x float4 = 1024 floats
    int p0 = d_pidx[t * 2], p1 = d_pidx[t * 2 + 1];
    const float* po0 = d_po2;
    const float* po1 = d_po2 + (size_t)(NEXP * SLOT * HDIM);
    float4 a = ((const float4*)(po0 + (size_t)p0 * HDIM))[i];
    float4 b = ((const float4*)(po0 + (size_t)p1 * HDIM))[i];
    float4 c = ((const float4*)(po1 + (size_t)p0 * HDIM))[i];
    float4 d = ((const float4*)(po1 + (size_t)p1 * HDIM))[i];
    float4 o;
    o.x = (a.x + c.x) + (b.x + d.x);
    o.y = (a.y + c.y) + (b.y + d.y);
    o.z = (a.z + c.z) + (b.z + d.z);
    o.w = (a.w + c.w) + (b.w + d.w);
    ((float4*)(out + (size_t)t * HDIM))[i] = o;
}

// ---------------- launch ----------------------------------------------------
extern "C" void kernel_launch(void* const* d_in, const int* in_sizes, int n_in,
                              void* d_out, int out_size) {
    const float* x  = (const float*)d_in[0];
    const float* gw = (const float*)d_in[1];
    const float* w1 = (const float*)d_in[2];
    const float* w2 = (const float*)d_in[3];
    const float* w3 = (const float*)d_in[4];
    float* out = (float*)d_out;

    const int smem1 = 9 * STG_F * 4;  // 82944 B
    const int smem2 = 6 * STG_F * 4;  // 55296 B
    cudaFuncSetAttribute(gemm1_kernel, cudaFuncAttributeMaxDynamicSharedMemorySize, smem1);
    cudaFuncSetAttribute(gemm2_kernel, cudaFuncAttributeMaxDynamicSharedMemorySize, smem2);

    init_kernel<<<1, 32>>>();
    routing_kernel<<<TOKS, 256>>>(x, gw);
    gemm1_kernel<<<dim3(FDIM / 64, NEXP * 8), 256, smem1>>>(x, w1, w3);
    gemm2_kernel<<<dim3(HDIM / 64, NEXP * 8, 2), 256, smem2>>>(w2);
    finalize_kernel<<<TOKS, 256>>>(out);
}